// round 1
// baseline (speedup 1.0000x reference)
#include <cuda_runtime.h>

#define NN 4096
#define INF 256
#define OF 64
#define NH 4

// Scratch (static device globals — no allocation in kernel_launch)
__device__ float    g_xt[NH][NN][OF];      // per-head transformed features
__device__ float4   g_idat[NH][NN];        // {src, exp(src), exp(0.2*src), 0}
__device__ float4   g_jdat[NH][NN];        // {dst, exp(dst), exp(0.2*dst), 0}
__device__ unsigned g_adjT[NN / 32][NN];   // adjacency bits, [wordcol][row] (transposed for coalesced loads)

typedef unsigned long long ull;

__device__ __forceinline__ ull dup2(float v) {
    ull r;
    asm("mov.b64 %0, {%1, %1};" : "=l"(r) : "f"(v));
    return r;
}
__device__ __forceinline__ void fma2(ull& d, ull a, ull b) {
    asm("fma.rn.f32x2 %0, %1, %2, %0;" : "+l"(d) : "l"(a), "l"(b));
}
__device__ __forceinline__ float2 unpack2(ull v) {
    float2 r;
    asm("mov.b64 {%0, %1}, %2;" : "=f"(r.x), "=f"(r.y) : "l"(v));
    return r;
}

// ---------------------------------------------------------------------------
// Kernel 1: pack adjacency into transposed bitmask g_adjT[wordcol][row]
// ---------------------------------------------------------------------------
__global__ void k_bitpack(const int* __restrict__ adj) {
    int gw   = (blockIdx.x * 256 + threadIdx.x) >> 5;  // global warp id
    int lane = threadIdx.x & 31;
    int row  = gw >> 7;        // 0..4095
    int wc   = gw & 127;       // 0..127
    unsigned m = __ballot_sync(0xffffffffu, adj[row * NN + wc * 32 + lane] > 0);
    if (lane == 0) g_adjT[wc][row] = m;
}

// ---------------------------------------------------------------------------
// Kernel 2: xt[h][n][f] = x[n,:] @ W[h,:,f]   (M=4096, K=256, per-head N=64)
// Block: 256 threads, 64x64 tile, 4x4 microtile, K-step 16.
// ---------------------------------------------------------------------------
__global__ __launch_bounds__(256) void k_xt(const float* __restrict__ x,
                                            const float* __restrict__ W) {
    __shared__ float sx[16][68];   // x^T chunk: sx[k][n]
    __shared__ float sw[16][64];   // W  chunk: sw[k][f]
    const int h  = blockIdx.y;
    const int n0 = blockIdx.x * 64;
    const int t  = threadIdx.x;
    const int tx = t & 15, ty = t >> 4;
    const float* Wh = W + h * INF * OF;

    float acc[4][4] = {};
    for (int k0 = 0; k0 < INF; k0 += 16) {
        // stage loads into registers first
        const int n  = t >> 2, kq = (t & 3) * 4;
        float4 xv = *(const float4*)(x + (n0 + n) * INF + k0 + kq);
        const int kk = t & 15, f4 = t >> 4;
        float4 wv = *(const float4*)(Wh + (kk + k0) * OF + f4 * 4);
        __syncthreads();   // previous compute done reading smem
        sx[kq + 0][n] = xv.x; sx[kq + 1][n] = xv.y;
        sx[kq + 2][n] = xv.z; sx[kq + 3][n] = xv.w;
        *(float4*)&sw[kk][f4 * 4] = wv;
        __syncthreads();
        #pragma unroll
        for (int k = 0; k < 16; k++) {
            float4 av = *(float4*)&sx[k][ty * 4];
            float4 bv = *(float4*)&sw[k][tx * 4];
            acc[0][0] += av.x * bv.x; acc[0][1] += av.x * bv.y; acc[0][2] += av.x * bv.z; acc[0][3] += av.x * bv.w;
            acc[1][0] += av.y * bv.x; acc[1][1] += av.y * bv.y; acc[1][2] += av.y * bv.z; acc[1][3] += av.y * bv.w;
            acc[2][0] += av.z * bv.x; acc[2][1] += av.z * bv.y; acc[2][2] += av.z * bv.z; acc[2][3] += av.z * bv.w;
            acc[3][0] += av.w * bv.x; acc[3][1] += av.w * bv.y; acc[3][2] += av.w * bv.z; acc[3][3] += av.w * bv.w;
        }
    }
    #pragma unroll
    for (int r = 0; r < 4; r++) {
        float4 o = make_float4(acc[r][0], acc[r][1], acc[r][2], acc[r][3]);
        *(float4*)&g_xt[h][n0 + ty * 4 + r][tx * 4] = o;
    }
}

// ---------------------------------------------------------------------------
// Kernel 3: per-(h,n) scalars: src/dst dot products -> exp tables
// One warp per (h,n); lane covers features {lane, lane+32}.
// ---------------------------------------------------------------------------
__global__ void k_rowdat(const float* __restrict__ a) {
    int gid  = (blockIdx.x * 256 + threadIdx.x) >> 5;
    int lane = threadIdx.x & 31;
    int h = gid >> 12, n = gid & (NN - 1);
    const float* xr = g_xt[h][n];
    const float* ah = a + h * 2 * OF;
    float v0 = xr[lane], v1 = xr[lane + 32];
    float src = v0 * ah[lane]      + v1 * ah[lane + 32];
    float dst = v0 * ah[64 + lane] + v1 * ah[96 + lane];
    #pragma unroll
    for (int s = 16; s; s >>= 1) {
        src += __shfl_xor_sync(0xffffffffu, src, s);
        dst += __shfl_xor_sync(0xffffffffu, dst, s);
    }
    if (lane == 0) {
        g_idat[h][n] = make_float4(src, expf(src), expf(0.2f * src), 0.f);
        g_jdat[h][n] = make_float4(dst, expf(dst), expf(0.2f * dst), 0.f);
    }
}

// ---------------------------------------------------------------------------
// Kernel 4 (main): per block = (head h, 64 i-rows). Loop over 64-wide j tiles:
//   stage A: build w[j][i] tile in smem (compare+select, no exp) + Z partials
//   stage B: acc[i][f] += w @ xt  via packed fma.rn.f32x2
// Epilogue: out = acc / Z
// ---------------------------------------------------------------------------
__global__ __launch_bounds__(256, 2) void k_main(float* __restrict__ out) {
    __shared__ float  ws[64][68];    // k(=j)-major weight tile, padded stride
    __shared__ float4 xts[64][16];   // xt tile: [k][f4]
    __shared__ float  zred[4][64];
    __shared__ float  zinv[64];

    const int h  = blockIdx.y;
    const int i0 = blockIdx.x * 64;
    const int t  = threadIdx.x;

    // stage-A identity: fixed i-row per thread, 16-wide j strip
    const int il = t & 63, jstrip = t >> 6;
    const float4 idat = g_idat[h][i0 + il];
    const float si = idat.x, A1 = idat.y, A2 = idat.z;
    float zacc = 0.f;

    // stage-B identity: 4 rows x 4 cols microtile
    const int tx = t & 15, ty = t >> 4;
    ull acc[4][2];
    #pragma unroll
    for (int r = 0; r < 4; r++) { acc[r][0] = 0ULL; acc[r][1] = 0ULL; }

    for (int jt = 0; jt < 64; jt++) {
        const int j0 = jt * 64;
        __syncthreads();  // previous stage B finished reading ws/xts

        // cooperative xt tile load (coalesced float4)
        #pragma unroll
        for (int e = 0; e < 4; e++) {
            int lin = t + e * 256;
            int k = lin >> 4, f4 = lin & 15;
            xts[k][f4] = *(const float4*)&g_xt[h][j0 + k][f4 * 4];
        }

        // stage A: adjacency bits (coalesced via transposed layout) + weights
        unsigned word = g_adjT[(j0 >> 5) + (jstrip >> 1)][i0 + il];
        unsigned bits = word >> ((jstrip & 1) * 16);
        #pragma unroll
        for (int e = 0; e < 16; e++) {
            int jl = jstrip * 16 + e;
            float4 jd = g_jdat[h][j0 + jl];             // warp-uniform L1 hit
            float c = si + jd.x;
            float w = (c >= 0.f) ? (A1 * jd.y) : (A2 * jd.z);
            w = ((bits >> e) & 1u) ? w : 0.f;
            zacc += w;
            ws[jl][il] = w;                             // conflict-free: il contiguous
        }
        __syncthreads();

        // stage B: 64x64x64 fp32 GEMM slab with packed f32x2 FMA
        #pragma unroll 4
        for (int k = 0; k < 64; k++) {
            float4 bv = xts[k][tx];
            ull b01, b23;
            asm("mov.b64 %0, {%1, %2};" : "=l"(b01) : "f"(bv.x), "f"(bv.y));
            asm("mov.b64 %0, {%1, %2};" : "=l"(b23) : "f"(bv.z), "f"(bv.w));
            float4 av = *(float4*)&ws[k][ty * 4];
            ull w0 = dup2(av.x), w1 = dup2(av.y), w2 = dup2(av.z), w3 = dup2(av.w);
            fma2(acc[0][0], w0, b01); fma2(acc[0][1], w0, b23);
            fma2(acc[1][0], w1, b01); fma2(acc[1][1], w1, b23);
            fma2(acc[2][0], w2, b01); fma2(acc[2][1], w2, b23);
            fma2(acc[3][0], w3, b01); fma2(acc[3][1], w3, b23);
        }
    }

    // reduce Z across the 4 j-strip threads per row
    zred[jstrip][il] = zacc;
    __syncthreads();
    if (t < 64) {
        float z = zred[0][t] + zred[1][t] + zred[2][t] + zred[3][t];
        zinv[t] = 1.0f / z;
    }
    __syncthreads();

    // epilogue: normalize and write out[n][h*64+f]
    #pragma unroll
    for (int r = 0; r < 4; r++) {
        int i = ty * 4 + r;
        float zi = zinv[i];
        float2 p0 = unpack2(acc[r][0]);
        float2 p1 = unpack2(acc[r][1]);
        float4 o = make_float4(p0.x * zi, p0.y * zi, p1.x * zi, p1.y * zi);
        *(float4*)&out[(i0 + i) * (NH * OF) + h * OF + tx * 4] = o;
    }
}

// ---------------------------------------------------------------------------
extern "C" void kernel_launch(void* const* d_in, const int* in_sizes, int n_in,
                              void* d_out, int out_size) {
    const float* x   = (const float*)d_in[0];  // [4096, 256]
    const float* W   = (const float*)d_in[1];  // [4, 256, 64]
    const float* a   = (const float*)d_in[2];  // [4, 128]
    const int*   adj = (const int*)d_in[3];    // [4096, 4096]
    float* out = (float*)d_out;                // [4096, 256]

    (void)in_sizes; (void)n_in; (void)out_size;

    k_bitpack<<<(NN * (NN / 32)) / 8, 256>>>(adj);
    k_xt<<<dim3(NN / 64, NH), 256>>>(x, W);
    k_rowdat<<<(NH * NN) / 8, 256>>>(a);
    k_main<<<dim3(NN / 64, NH), 256>>>(out);
}